// round 16
// baseline (speedup 1.0000x reference)
#include <cuda_runtime.h>
#include <cuda_bf16.h>
#include <cstdint>

#define NN 32768
#define FD 128
#define NE 262144
#define NL 64

// ---------------- scratch ----------------
__device__ float g_h0[NN * FD];                 // activations ping-pong (fp32)
__device__ float g_h1[NN * FD];
__device__ float g_dinv[NN];
__device__ float g_selfw[NN];
__device__ __align__(16) int g_cnt[NN];
__device__ int   g_cur[NN];
__device__ __align__(16) int g_row[NN + 4];
__device__ int   g_src[NE];
__device__ int   g_dst[NE];
__device__ int2  g_edge[NE];                    // {src, weight bits}
__device__ int   g_is64;
__device__ __nv_bfloat16 g_wh[NL * 16384];      // [l][n][k] transposed
__device__ __nv_bfloat16 g_wl[NL * 16384];

// ---------------- helpers ----------------
__device__ __forceinline__ uint32_t smem_u32(const void* p) {
    uint32_t a;
    asm("{ .reg .u64 t; cvta.to.shared.u64 t, %1; cvt.u32.u64 %0, t; }"
        : "=r"(a) : "l"(p));
    return a;
}
__device__ __forceinline__ void ldm_x4(uint32_t* r, uint32_t addr) {
    asm volatile("ldmatrix.sync.aligned.m8n8.x4.shared.b16 {%0,%1,%2,%3}, [%4];"
                 : "=r"(r[0]), "=r"(r[1]), "=r"(r[2]), "=r"(r[3]) : "r"(addr));
}
__device__ __forceinline__ void mma16816(float* c, const uint32_t* a,
                                         uint32_t b0, uint32_t b1) {
    asm volatile(
        "mma.sync.aligned.m16n8k16.row.col.f32.bf16.bf16.f32 "
        "{%0,%1,%2,%3}, {%4,%5,%6,%7}, {%8,%9}, {%0,%1,%2,%3};"
        : "+f"(c[0]), "+f"(c[1]), "+f"(c[2]), "+f"(c[3])
        : "r"(a[0]), "r"(a[1]), "r"(a[2]), "r"(a[3]), "r"(b0), "r"(b1));
}
__device__ __forceinline__ void split4(float4 a, uint32_t& h01, uint32_t& h23,
                                       uint32_t& l01, uint32_t& l23) {
    asm("cvt.rn.bf16x2.f32 %0, %1, %2;" : "=r"(h01) : "f"(a.y), "f"(a.x));
    asm("cvt.rn.bf16x2.f32 %0, %1, %2;" : "=r"(h23) : "f"(a.w), "f"(a.z));
    float hx = __uint_as_float(h01 << 16);
    float hy = __uint_as_float(h01 & 0xffff0000u);
    float hz = __uint_as_float(h23 << 16);
    float hw_ = __uint_as_float(h23 & 0xffff0000u);
    asm("cvt.rn.bf16x2.f32 %0, %1, %2;" : "=r"(l01) : "f"(a.y - hy), "f"(a.x - hx));
    asm("cvt.rn.bf16x2.f32 %0, %1, %2;" : "=r"(l23) : "f"(a.w - hw_), "f"(a.z - hz));
}
#define CP_ASYNC16(dst, src) \
    asm volatile("cp.async.ca.shared.global [%0], [%1], 16;" \
                 :: "r"(dst), "l"(src) : "memory")

// ---------------- setup kernels ----------------
__global__ void detect_kernel(const int* __restrict__ ei) {
    if (threadIdx.x == 0 && blockIdx.x == 0) {
        int odd_zero = 1;
        for (int i = 0; i < 64; i++)
            if (ei[2 * i + 1] != 0) { odd_zero = 0; break; }
        g_is64 = odd_zero;
    }
}
__global__ void zero_kernel() {
    int i = blockIdx.x * blockDim.x + threadIdx.x;
    if (i < NN) { g_cnt[i] = 0; g_cur[i] = 0; }
}
__global__ void convert_count_kernel(const int* __restrict__ ei) {
    int e = blockIdx.x * blockDim.x + threadIdx.x;
    if (e >= NE) return;
    int s, d;
    if (g_is64) {
        const long long* p = (const long long*)ei;
        s = (int)p[e];
        d = (int)p[NE + e];
    } else {
        s = ei[e];
        d = ei[NE + e];
    }
    g_src[e] = s;
    g_dst[e] = d;
    atomicAdd(&g_cnt[d], 1);
}
__global__ void scan_kernel() {
    __shared__ int sh[1024];
    int t = threadIdx.x;
    const int4* cnt4 = (const int4*)g_cnt;
    int4 c[8];
    int s = 0;
#pragma unroll
    for (int i = 0; i < 8; i++) {
        c[i] = cnt4[t * 8 + i];
        s += c[i].x + c[i].y + c[i].z + c[i].w;
    }
    sh[t] = s;
    __syncthreads();
    for (int off = 1; off < 1024; off <<= 1) {
        int v = (t >= off) ? sh[t - off] : 0;
        __syncthreads();
        sh[t] += v;
        __syncthreads();
    }
    int run = (t == 0) ? 0 : sh[t - 1];
    int4* row4 = (int4*)g_row;
#pragma unroll
    for (int i = 0; i < 8; i++) {
        int4 v;
        v.x = run; run += c[i].x;
        v.y = run; run += c[i].y;
        v.z = run; run += c[i].z;
        v.w = run; run += c[i].w;
        row4[t * 8 + i] = v;
    }
    if (t == 1023) g_row[NN] = run;
}
__global__ void dinv_kernel() {
    int v = blockIdx.x * blockDim.x + threadIdx.x;
    if (v >= NN) return;
    float deg = (float)(g_cnt[v] + 1);
    float di = 1.0f / sqrtf(deg);
    g_dinv[v] = di;
    g_selfw[v] = di * di;
}
__global__ void scatter_kernel() {
    int e = blockIdx.x * blockDim.x + threadIdx.x;
    if (e >= NE) return;
    int s = g_src[e];
    int d = g_dst[e];
    int pos = g_row[d] + atomicAdd(&g_cur[d], 1);
    g_edge[pos] = make_int2(s, __float_as_int(g_dinv[s] * g_dinv[d]));
}
__global__ void wsplit_kernel(const float* __restrict__ wts) {
    int idx = blockIdx.x * blockDim.x + threadIdx.x;
    if (idx >= NL * 16384) return;
    int l = idx >> 14;
    int e = idx & 16383;
    int k = e >> 7;
    int n = e & 127;
    float v = wts[idx];
    __nv_bfloat16 hi = __float2bfloat16(v);
    float hf = __bfloat162float(hi);
    __nv_bfloat16 lo = __float2bfloat16(v - hf);
    int o = (l << 14) + n * 128 + k;
    g_wh[o] = hi;
    g_wl[o] = lo;
}

// ---------------- fused layer: h' = relu(agg(h) @ W + b) ----------------
#define PITCH 136
#define TILE_BYTES (128 * PITCH * 2)
#define OFF_WH   0
#define OFF_WL   (TILE_BYTES)
#define OFF_A0H  (2 * TILE_BYTES)
#define OFF_A0L  (3 * TILE_BYTES)
#define OFF_A1H  (4 * TILE_BYTES)
#define OFF_A1L  (5 * TILE_BYTES)
#define OFF_BIAS (6 * TILE_BYTES)
#define SM_SZ    (6 * TILE_BYTES + 512)

__global__ void __launch_bounds__(256) layer_kernel(const float* __restrict__ x,
                                                    const float* __restrict__ bias,
                                                    int layer) {
    extern __shared__ char sm[];
    uint32_t sbase = smem_u32(sm);

    int t = threadIdx.x;
    int w = t >> 5;
    int lane = t & 31;
    int wrow = w * 16;

    const float4* __restrict__ h4 =
        (layer == 0) ? (const float4*)x
                     : (const float4*)((layer & 1) ? g_h0 : g_h1);
    float* __restrict__ hout = (layer & 1) ? g_h1 : g_h0;

    // --- W hi/lo + bias via cp.async (streams in during gather) ---
    {
        const __nv_bfloat16* wh = g_wh + ((size_t)layer << 14);
        const __nv_bfloat16* wl = g_wl + ((size_t)layer << 14);
#pragma unroll
        for (int i = 0; i < 8; i++) {
            int idx8 = t + i * 256;
            int n = idx8 >> 4;
            int k8 = (idx8 & 15) << 3;
            uint32_t doff = (uint32_t)((n * PITCH + k8) * 2);
            CP_ASYNC16(sbase + OFF_WH + doff, wh + idx8 * 8);
            CP_ASYNC16(sbase + OFF_WL + doff, wl + idx8 * 8);
        }
        if (t < 32) CP_ASYNC16(sbase + OFF_BIAS + t * 16, bias + t * 4);
        asm volatile("cp.async.commit_group;" ::: "memory");
    }

    // --- gather phase: s = agg(h) for this CTA's 256 rows, split into sA ---
#pragma unroll 1
    for (int grp = 0; grp < 4; grp++) {
        int tile = grp >> 1;
        int rbase = wrow + (grp & 1) * 8;          // row within tile
        int vbase = blockIdx.x * 256 + tile * 128 + rbase;

        int beg[8], end[8];
#pragma unroll
        for (int i = 0; i < 8; i++) {
            beg[i] = g_row[vbase + i];
            end[i] = g_row[vbase + i + 1];
        }
        float4 acc[8];
#pragma unroll
        for (int i = 0; i < 8; i++) {
            float sw = g_selfw[vbase + i];
            float4 hv = h4[(size_t)(vbase + i) * 32 + lane];
            acc[i] = make_float4(sw * hv.x, sw * hv.y, sw * hv.z, sw * hv.w);
        }
        int maxd = 0;
#pragma unroll
        for (int i = 0; i < 8; i++) maxd = max(maxd, end[i] - beg[i]);

        int2 edc[8];
#pragma unroll
        for (int i = 0; i < 8; i++) {
            edc[i] = make_int2(0, 0);
            if (beg[i] < end[i]) edc[i] = g_edge[beg[i]];
        }
        for (int j = 0; j < maxd; j++) {
            int2 edn[8];
#pragma unroll
            for (int i = 0; i < 8; i++) {
                edn[i] = make_int2(0, 0);
                int ix = beg[i] + j + 1;
                if (ix < end[i]) edn[i] = g_edge[ix];
            }
            float4 u[8];
#pragma unroll
            for (int i = 0; i < 8; i++) {
                if (beg[i] + j < end[i])
                    u[i] = h4[(size_t)edc[i].x * 32 + lane];
            }
#pragma unroll
            for (int i = 0; i < 8; i++) {
                if (beg[i] + j < end[i]) {
                    float wt = __int_as_float(edc[i].y);
                    acc[i].x += wt * u[i].x;
                    acc[i].y += wt * u[i].y;
                    acc[i].z += wt * u[i].z;
                    acc[i].w += wt * u[i].w;
                }
            }
#pragma unroll
            for (int i = 0; i < 8; i++) edc[i] = edn[i];
        }

        // split s rows -> bf16 hi/lo smem A tiles (warp-private rows)
        char* dH = sm + (tile ? OFF_A1H : OFF_A0H);
        char* dL = sm + (tile ? OFF_A1L : OFF_A0L);
#pragma unroll
        for (int i = 0; i < 8; i++) {
            uint32_t h01, h23, l01, l23;
            split4(acc[i], h01, h23, l01, l23);
            *(uint2*)(dH + (rbase + i) * (PITCH * 2) + lane * 8) = make_uint2(h01, h23);
            *(uint2*)(dL + (rbase + i) * (PITCH * 2) + lane * 8) = make_uint2(l01, l23);
        }
    }

    asm volatile("cp.async.wait_group 0;" ::: "memory");
    __syncthreads();

    // --- MMA: 3-pass bf16 split, both tiles, ks-outer (validated round-14) ---
    int g = lane >> 2;
    int q = lane & 3;
    uint32_t aRowOff = (uint32_t)((wrow + (lane & 15)) * (PITCH * 2) +
                                  ((lane >> 4) * 8) * 2);
    uint32_t addrA0h = sbase + OFF_A0H + aRowOff;
    uint32_t addrA0l = sbase + OFF_A0L + aRowOff;
    uint32_t addrA1h = sbase + OFF_A1H + aRowOff;
    uint32_t addrA1l = sbase + OFF_A1L + aRowOff;
    uint32_t bLaneOff = (uint32_t)((((lane & 7) + ((lane >> 4) << 3)) * PITCH) * 2 +
                                   ((lane >> 3) & 1) * 16);
    uint32_t addrBh = sbase + OFF_WH + bLaneOff;
    uint32_t addrBl = sbase + OFF_WL + bLaneOff;

    float acc0[16][4], acc1[16][4];
#pragma unroll
    for (int i = 0; i < 16; i++)
#pragma unroll
        for (int j = 0; j < 4; j++) { acc0[i][j] = 0.0f; acc1[i][j] = 0.0f; }

#pragma unroll
    for (int ks = 0; ks < 8; ks++) {
        uint32_t a0h[4], a0l[4], a1h[4], a1l[4];
        ldm_x4(a0h, addrA0h + ks * 32);
        ldm_x4(a0l, addrA0l + ks * 32);
        ldm_x4(a1h, addrA1h + ks * 32);
        ldm_x4(a1l, addrA1l + ks * 32);
#pragma unroll
        for (int p = 0; p < 8; p++) {
            uint32_t bh[4], bl[4];
            uint32_t boff = (uint32_t)(p * (16 * PITCH * 2) + ks * 32);
            ldm_x4(bh, addrBh + boff);
            ldm_x4(bl, addrBl + boff);
            int n0 = p * 2, n1 = n0 + 1;
            mma16816(acc0[n0], a0h, bh[0], bh[1]);
            mma16816(acc0[n1], a0h, bh[2], bh[3]);
            mma16816(acc1[n0], a1h, bh[0], bh[1]);
            mma16816(acc1[n1], a1h, bh[2], bh[3]);
            mma16816(acc0[n0], a0h, bl[0], bl[1]);
            mma16816(acc0[n1], a0h, bl[2], bl[3]);
            mma16816(acc1[n0], a1h, bl[0], bl[1]);
            mma16816(acc1[n1], a1h, bl[2], bl[3]);
            mma16816(acc0[n0], a0l, bh[0], bh[1]);
            mma16816(acc0[n1], a0l, bh[2], bh[3]);
            mma16816(acc1[n0], a1l, bh[0], bh[1]);
            mma16816(acc1[n1], a1l, bh[2], bh[3]);
        }
    }

    // --- epilogue: bias + relu, float2 stores ---
    {
        const float* sBias = (const float*)(sm + OFF_BIAS);
        int tb0 = blockIdx.x * 256;
#pragma unroll
        for (int nt = 0; nt < 16; nt++) {
            int col = nt * 8 + q * 2;
            float2 bv = *(const float2*)&sBias[col];
            int r0 = tb0 + wrow + g;
            *(float2*)&hout[(size_t)r0 * 128 + col] =
                make_float2(fmaxf(acc0[nt][0] + bv.x, 0.0f),
                            fmaxf(acc0[nt][1] + bv.y, 0.0f));
            *(float2*)&hout[(size_t)(r0 + 8) * 128 + col] =
                make_float2(fmaxf(acc0[nt][2] + bv.x, 0.0f),
                            fmaxf(acc0[nt][3] + bv.y, 0.0f));
            int r1 = tb0 + 128 + wrow + g;
            *(float2*)&hout[(size_t)r1 * 128 + col] =
                make_float2(fmaxf(acc1[nt][0] + bv.x, 0.0f),
                            fmaxf(acc1[nt][1] + bv.y, 0.0f));
            *(float2*)&hout[(size_t)(r1 + 8) * 128 + col] =
                make_float2(fmaxf(acc1[nt][2] + bv.x, 0.0f),
                            fmaxf(acc1[nt][3] + bv.y, 0.0f));
        }
    }
}

// ---------------- final: out = (h64 + x) @ cls_w + cls_b ----------------
__global__ void __launch_bounds__(256) final_kernel(const float* __restrict__ x,
                                                    const float* __restrict__ cw,
                                                    const float* __restrict__ cb,
                                                    float* __restrict__ out) {
    int node = (blockIdx.x * blockDim.x + threadIdx.x) >> 5;
    int lane = threadIdx.x & 31;
    if (node >= NN) return;

    // layer 63 wrote g_h1 (63 & 1)
    float4 hv = ((const float4*)g_h1)[(size_t)node * 32 + lane];
    float4 xv = ((const float4*)x)[(size_t)node * 32 + lane];
    hv.x += xv.x; hv.y += xv.y; hv.z += xv.z; hv.w += xv.w;

    const float4* w4 = (const float4*)cw;
    int f0 = lane * 4;
    float4 w0 = w4[f0], w1 = w4[f0 + 1], w2 = w4[f0 + 2], w3 = w4[f0 + 3];
    float4 p;
    p.x = hv.x * w0.x + hv.y * w1.x + hv.z * w2.x + hv.w * w3.x;
    p.y = hv.x * w0.y + hv.y * w1.y + hv.z * w2.y + hv.w * w3.y;
    p.z = hv.x * w0.z + hv.y * w1.z + hv.z * w2.z + hv.w * w3.z;
    p.w = hv.x * w0.w + hv.y * w1.w + hv.z * w2.w + hv.w * w3.w;

#pragma unroll
    for (int off = 16; off; off >>= 1) {
        p.x += __shfl_xor_sync(0xffffffffu, p.x, off);
        p.y += __shfl_xor_sync(0xffffffffu, p.y, off);
        p.z += __shfl_xor_sync(0xffffffffu, p.z, off);
        p.w += __shfl_xor_sync(0xffffffffu, p.w, off);
    }
    if (lane == 0) {
        float4 b = *(const float4*)cb;
        p.x += b.x; p.y += b.y; p.z += b.z; p.w += b.w;
        ((float4*)out)[node] = p;
    }
}

// ---------------- launch ----------------
extern "C" void kernel_launch(void* const* d_in, const int* in_sizes, int n_in,
                              void* d_out, int out_size) {
    const float* x      = (const float*)d_in[0];
    const int*   ei     = (const int*)d_in[1];
    const float* wts    = (const float*)d_in[2];
    const float* biases = (const float*)d_in[3];
    const float* cls_w  = (const float*)d_in[4];
    const float* cls_b  = (const float*)d_in[5];
    float* out = (float*)d_out;

    cudaFuncSetAttribute(layer_kernel, cudaFuncAttributeMaxDynamicSharedMemorySize,
                         SM_SZ);

    detect_kernel<<<1, 32>>>(ei);
    zero_kernel<<<NN / 256, 256>>>();
    convert_count_kernel<<<NE / 256, 256>>>(ei);
    scan_kernel<<<1, 1024>>>();
    dinv_kernel<<<NN / 256, 256>>>();
    scatter_kernel<<<NE / 256, 256>>>();
    wsplit_kernel<<<NL * 16384 / 256, 256>>>(wts);

    for (int l = 0; l < NL; l++)
        layer_kernel<<<128, 256, SM_SZ>>>(x, biases + (size_t)l * 128, l);

    final_kernel<<<NN / 8, 256>>>(x, cls_w, cls_b, out);
}